// round 4
// baseline (speedup 1.0000x reference)
#include <cuda_runtime.h>
#include <cuda_fp16.h>
#include <cstdint>

// ============================================================================
// EdgeMLP: f = MLP(edges[:, :3]); out[i][j] = (cls1[i]==cls2[j]) * cos(f1[i],f2[j])
// Round 4: HMMA m16n8k16; 64x128 CTA tile, 32x32 warp tile, STG.128 epilogue
// via lane-pair shuffle, streaming stores, occupancy 3 CTAs/SM.
// ============================================================================

#define N_MAX 8192
#define KK 32

__device__ __half g_h1[N_MAX * KK];
__device__ __half g_h2[N_MAX * KK];
__device__ int    g_c1[N_MAX];
__device__ int    g_c2[N_MAX];

// ----------------------------------------------------------------------------
// Kernel 1: MLP + normalize, 4 threads per row (each 8 of 32 outputs).
// ----------------------------------------------------------------------------
__global__ void __launch_bounds__(256) feat_kernel(
    const float* __restrict__ e1, const float* __restrict__ e2, int N1, int N2,
    const float* __restrict__ W1, const float* __restrict__ b1,
    const float* __restrict__ W2, const float* __restrict__ b2)
{
    __shared__ float sW1[192], sb1[64], sW2[2048], sb2[32];
    int t = threadIdx.x;
    for (int i = t; i < 192;  i += 256) sW1[i] = W1[i];
    if (t < 64) sb1[t] = b1[t];
    for (int i = t; i < 2048; i += 256) sW2[i] = W2[i];
    if (t < 32) sb2[t] = b2[t];
    __syncthreads();

    int gid  = blockIdx.x * 256 + t;
    int row2 = gid >> 2;
    int s    = gid & 3;
    if (row2 >= N1 + N2) return;

    const float* ed; __half* fo; int* co; int row;
    if (row2 < N1) { ed = e1; fo = g_h1; co = g_c1; row = row2; }
    else           { ed = e2; fo = g_h2; co = g_c2; row = row2 - N1; }

    float4 e = reinterpret_cast<const float4*>(ed)[row];

    float f[8];
    #pragma unroll
    for (int q = 0; q < 8; q++) f[q] = sb2[s * 8 + q];

    #pragma unroll 8
    for (int k = 0; k < 64; k++) {
        float h = fmaf(e.x, sW1[k], fmaf(e.y, sW1[64 + k], fmaf(e.z, sW1[128 + k], sb1[k])));
        h = fmaxf(h, 0.0f);
        const float4* w = reinterpret_cast<const float4*>(&sW2[k * 32 + s * 8]);
        float4 w0 = w[0], w1 = w[1];
        f[0] = fmaf(h, w0.x, f[0]); f[1] = fmaf(h, w0.y, f[1]);
        f[2] = fmaf(h, w0.z, f[2]); f[3] = fmaf(h, w0.w, f[3]);
        f[4] = fmaf(h, w1.x, f[4]); f[5] = fmaf(h, w1.y, f[5]);
        f[6] = fmaf(h, w1.z, f[6]); f[7] = fmaf(h, w1.w, f[7]);
    }

    float p = 0.0f;
    #pragma unroll
    for (int q = 0; q < 8; q++) p = fmaf(f[q], f[q], p);
    p += __shfl_xor_sync(0xFFFFFFFFu, p, 1);
    p += __shfl_xor_sync(0xFFFFFFFFu, p, 2);
    float inv = rsqrtf(fmaxf(p, 1e-24f));

    __half2 o[4];
    #pragma unroll
    for (int q = 0; q < 4; q++)
        o[q] = __floats2half2_rn(f[2 * q] * inv, f[2 * q + 1] * inv);
    *reinterpret_cast<uint4*>(fo + (size_t)row * KK + s * 8) = *reinterpret_cast<uint4*>(o);
    if (s == 0) co[row] = (int)e.w;
}

// ----------------------------------------------------------------------------
__device__ __forceinline__ void hmma16816(float c[4], const uint32_t a[4], const uint32_t b[2]) {
    asm volatile(
        "mma.sync.aligned.m16n8k16.row.col.f32.f16.f16.f32 "
        "{%0,%1,%2,%3}, {%4,%5,%6,%7}, {%8,%9}, {%0,%1,%2,%3};"
        : "+f"(c[0]), "+f"(c[1]), "+f"(c[2]), "+f"(c[3])
        : "r"(a[0]), "r"(a[1]), "r"(a[2]), "r"(a[3]), "r"(b[0]), "r"(b[1]));
}

// ----------------------------------------------------------------------------
// Kernel 2: 64x128 output tile per CTA, 256 threads = 8 warps (2 M x 4 N),
// each warp a 32x32 sub-tile. Epilogue: lane-pair shuffle -> STG.128 streaming.
// ----------------------------------------------------------------------------
#define RS 40   // smem row stride in halves (80B, conflict-free)

__global__ void __launch_bounds__(256, 3) pair_kernel(float* __restrict__ out, int N2)
{
    __shared__ __half As[64][RS];
    __shared__ __half Bs[128][RS];
    __shared__ int sc1[64], sc2[128];

    int t    = threadIdx.x;
    int wid  = t >> 5;
    int lane = t & 31;
    int i0   = blockIdx.y * 64;
    int j0   = blockIdx.x * 128;

    // --- Load tiles: A 64 rows, B 128 rows, 4 uint4 chunks per row ---
    #pragma unroll
    for (int p = 0; p < 3; p++) {
        int idx = t + p * 256;            // 0..767
        if (idx < 256) {
            int row = idx >> 2, c16 = idx & 3;
            uint4 a = reinterpret_cast<const uint4*>(g_h1 + (size_t)(i0 + row) * KK)[c16];
            *reinterpret_cast<uint4*>(&As[row][c16 * 8]) = a;
        } else {
            int v = idx - 256;
            int row = v >> 2, c16 = v & 3;
            uint4 b = reinterpret_cast<const uint4*>(g_h2 + (size_t)(j0 + row) * KK)[c16];
            *reinterpret_cast<uint4*>(&Bs[row][c16 * 8]) = b;
        }
    }
    if (t < 64) sc1[t] = g_c1[i0 + t];
    else if (t < 192) sc2[t - 64] = g_c2[j0 + (t - 64)];
    __syncthreads();

    int warp_m = wid >> 2;     // 0..1
    int warp_n = wid & 3;      // 0..3
    int r4 = lane >> 2;        // 0..7
    int c2 = (lane & 3) * 2;   // 0,2,4,6

    float acc[2][4][4];
    #pragma unroll
    for (int mt = 0; mt < 2; mt++)
        #pragma unroll
        for (int nt = 0; nt < 4; nt++)
            #pragma unroll
            for (int q = 0; q < 4; q++) acc[mt][nt][q] = 0.0f;

    #pragma unroll
    for (int k = 0; k < 2; k++) {
        int kc = c2 + k * 16;

        uint32_t af[2][4];
        #pragma unroll
        for (int mt = 0; mt < 2; mt++) {
            int row = warp_m * 32 + mt * 16 + r4;
            af[mt][0] = *reinterpret_cast<const uint32_t*>(&As[row    ][kc    ]);
            af[mt][1] = *reinterpret_cast<const uint32_t*>(&As[row + 8][kc    ]);
            af[mt][2] = *reinterpret_cast<const uint32_t*>(&As[row    ][kc + 8]);
            af[mt][3] = *reinterpret_cast<const uint32_t*>(&As[row + 8][kc + 8]);
        }
        uint32_t bf[4][2];
        #pragma unroll
        for (int nt = 0; nt < 4; nt++) {
            int col = warp_n * 32 + nt * 8 + r4;
            bf[nt][0] = *reinterpret_cast<const uint32_t*>(&Bs[col][kc    ]);
            bf[nt][1] = *reinterpret_cast<const uint32_t*>(&Bs[col][kc + 8]);
        }

        #pragma unroll
        for (int mt = 0; mt < 2; mt++)
            #pragma unroll
            for (int nt = 0; nt < 4; nt++)
                hmma16816(acc[mt][nt], af[mt], bf[nt]);
    }

    // --- Epilogue: mask, lane-pair shuffle to form float4, streaming STG.128 ---
    int cn[4][2];
    #pragma unroll
    for (int nt = 0; nt < 4; nt++) {
        cn[nt][0] = sc2[warp_n * 32 + nt * 8 + c2];
        cn[nt][1] = sc2[warp_n * 32 + nt * 8 + c2 + 1];
    }

    int odd  = lane & 1;
    int cp4  = ((lane >> 1) & 1) * 4;                 // column-pair base: 0 or 4
    float* outw = out + (size_t)j0 + warp_n * 32 + cp4;

    #pragma unroll
    for (int mt = 0; mt < 2; mt++) {
        int rA  = warp_m * 32 + mt * 16 + r4;
        int cmA = sc1[rA];
        int cmB = sc1[rA + 8];
        int rowg = i0 + rA + odd * 8;
        float* orow = outw + (size_t)rowg * (size_t)N2;

        #pragma unroll
        for (int nt = 0; nt < 4; nt++) {
            float v0 = (cmA == cn[nt][0]) ? acc[mt][nt][0] : 0.0f;
            float v1 = (cmA == cn[nt][1]) ? acc[mt][nt][1] : 0.0f;
            float v2 = (cmB == cn[nt][0]) ? acc[mt][nt][2] : 0.0f;
            float v3 = (cmB == cn[nt][1]) ? acc[mt][nt][3] : 0.0f;
            float t0 = __shfl_xor_sync(0xFFFFFFFFu, v0, 1);
            float t1 = __shfl_xor_sync(0xFFFFFFFFu, v1, 1);
            float t2 = __shfl_xor_sync(0xFFFFFFFFu, v2, 1);
            float t3 = __shfl_xor_sync(0xFFFFFFFFu, v3, 1);
            // even lane: row rA,   cols [c..c+3] = (v0, v1, t0, t1)
            // odd  lane: row rA+8, cols [c..c+3] = (t2, t3, v2, v3)
            float4 o;
            o.x = odd ? t2 : v0;
            o.y = odd ? t3 : v1;
            o.z = odd ? v2 : t0;
            o.w = odd ? v3 : t1;
            __stcs(reinterpret_cast<float4*>(orow + nt * 8), o);
        }
    }
}

// ----------------------------------------------------------------------------
extern "C" void kernel_launch(void* const* d_in, const int* in_sizes, int n_in,
                              void* d_out, int out_size)
{
    const float* edges1 = (const float*)d_in[0];
    const float* edges2 = (const float*)d_in[1];
    const float* W1     = (const float*)d_in[2];
    const float* b1     = (const float*)d_in[3];
    const float* W2     = (const float*)d_in[4];
    const float* b2     = (const float*)d_in[5];
    float* out = (float*)d_out;

    int N1 = in_sizes[0] / 4;
    int N2 = in_sizes[1] / 4;

    int totalThreads = (N1 + N2) * 4;
    feat_kernel<<<(totalThreads + 255) / 256, 256>>>(edges1, edges2, N1, N2, W1, b1, W2, b2);

    dim3 grid(N2 / 128, N1 / 64);
    pair_kernel<<<grid, 256>>>(out, N2);
}

// round 5
// speedup vs baseline: 1.2315x; 1.2315x over previous
#include <cuda_runtime.h>
#include <cuda_fp16.h>
#include <cstdint>

// ============================================================================
// EdgeMLP: f = MLP(edges[:, :3]); out[i][j] = (cls1[i]==cls2[j]) * cos(f1[i],f2[j])
// Round 5: HMMA m16n8k16, 128x128 CTA tile, 64x32 warp tile.
// Column-permuted B tile => epilogue is shuffle-free STG.128 with 64B/row
// contiguous segments per warp store (halves L1 store wavefronts vs round 3).
// ============================================================================

#define N_MAX 8192
#define KK 32

__device__ __half g_h1[N_MAX * KK];
__device__ __half g_h2[N_MAX * KK];
__device__ int    g_c1[N_MAX];
__device__ int    g_c2[N_MAX];

// ----------------------------------------------------------------------------
// Kernel 1: MLP + normalize, 4 threads per row (each 8 of 32 outputs).
// ----------------------------------------------------------------------------
__global__ void __launch_bounds__(256) feat_kernel(
    const float* __restrict__ e1, const float* __restrict__ e2, int N1, int N2,
    const float* __restrict__ W1, const float* __restrict__ b1,
    const float* __restrict__ W2, const float* __restrict__ b2)
{
    __shared__ float sW1[192], sb1[64], sW2[2048], sb2[32];
    int t = threadIdx.x;
    for (int i = t; i < 192;  i += 256) sW1[i] = W1[i];
    if (t < 64) sb1[t] = b1[t];
    for (int i = t; i < 2048; i += 256) sW2[i] = W2[i];
    if (t < 32) sb2[t] = b2[t];
    __syncthreads();

    int gid  = blockIdx.x * 256 + t;
    int row2 = gid >> 2;
    int s    = gid & 3;
    if (row2 >= N1 + N2) return;

    const float* ed; __half* fo; int* co; int row;
    if (row2 < N1) { ed = e1; fo = g_h1; co = g_c1; row = row2; }
    else           { ed = e2; fo = g_h2; co = g_c2; row = row2 - N1; }

    float4 e = reinterpret_cast<const float4*>(ed)[row];

    float f[8];
    #pragma unroll
    for (int q = 0; q < 8; q++) f[q] = sb2[s * 8 + q];

    #pragma unroll 8
    for (int k = 0; k < 64; k++) {
        float h = fmaf(e.x, sW1[k], fmaf(e.y, sW1[64 + k], fmaf(e.z, sW1[128 + k], sb1[k])));
        h = fmaxf(h, 0.0f);
        const float4* w = reinterpret_cast<const float4*>(&sW2[k * 32 + s * 8]);
        float4 w0 = w[0], w1 = w[1];
        f[0] = fmaf(h, w0.x, f[0]); f[1] = fmaf(h, w0.y, f[1]);
        f[2] = fmaf(h, w0.z, f[2]); f[3] = fmaf(h, w0.w, f[3]);
        f[4] = fmaf(h, w1.x, f[4]); f[5] = fmaf(h, w1.y, f[5]);
        f[6] = fmaf(h, w1.z, f[6]); f[7] = fmaf(h, w1.w, f[7]);
    }

    float p = 0.0f;
    #pragma unroll
    for (int q = 0; q < 8; q++) p = fmaf(f[q], f[q], p);
    p += __shfl_xor_sync(0xFFFFFFFFu, p, 1);
    p += __shfl_xor_sync(0xFFFFFFFFu, p, 2);
    float inv = rsqrtf(fmaxf(p, 1e-24f));

    __half2 o[4];
    #pragma unroll
    for (int q = 0; q < 4; q++)
        o[q] = __floats2half2_rn(f[2 * q] * inv, f[2 * q + 1] * inv);
    *reinterpret_cast<uint4*>(fo + (size_t)row * KK + s * 8) = *reinterpret_cast<uint4*>(o);
    if (s == 0) co[row] = (int)e.w;
}

// ----------------------------------------------------------------------------
__device__ __forceinline__ void hmma16816(float c[4], const uint32_t a[4], const uint32_t b[2]) {
    asm volatile(
        "mma.sync.aligned.m16n8k16.row.col.f32.f16.f16.f32 "
        "{%0,%1,%2,%3}, {%4,%5,%6,%7}, {%8,%9}, {%0,%1,%2,%3};"
        : "+f"(c[0]), "+f"(c[1]), "+f"(c[2]), "+f"(c[3])
        : "r"(a[0]), "r"(a[1]), "r"(a[2]), "r"(a[3]), "r"(b[0]), "r"(b[1]));
}

// Column permutation (within each 32-col slab):
//   global col j (bits s,q1,q0,n1,e = j[4],j[3:2],j[1],j[0])
//   -> smem row   (bits s,n1,q1,q0,e)
// so that mma tile nt = 2s+n1, fragment col c = 2q+e holds global col
//   perm(nt,c) = 16s + 4q + 2*n1 + e  => thread q's (nt,nt+1) outputs are
//   4 contiguous global columns.
__device__ __forceinline__ int bperm_row(int j) {
    int jl = j & 31;
    int r  = ((jl >> 4) & 1) * 16 + ((jl >> 1) & 1) * 8 + ((jl >> 2) & 3) * 2 + (jl & 1);
    return (j & ~31) + r;
}

// ----------------------------------------------------------------------------
// Kernel 2: 128x128 tile, 256 threads = 8 warps (2 M x 4 N), warp = 64x32.
// ----------------------------------------------------------------------------
#define RS 40   // smem row stride in halves (80B, conflict-free fragment loads)

__global__ void __launch_bounds__(256, 2) pair_kernel(float* __restrict__ out, int N2)
{
    __shared__ __half As[128][RS];
    __shared__ __half Bs[128][RS];
    __shared__ int sc1[128], sc2[128];

    int t    = threadIdx.x;
    int wid  = t >> 5;
    int lane = t & 31;
    int i0   = blockIdx.y * 128;
    int j0   = blockIdx.x * 128;

    // --- Load tiles (B column-permuted across smem rows) ---
    #pragma unroll
    for (int p = 0; p < 2; p++) {
        int chunk = t + p * 256;          // 0..511
        int row   = chunk >> 2;
        int c16   = chunk & 3;
        uint4 a = reinterpret_cast<const uint4*>(g_h1 + (size_t)(i0 + row) * KK)[c16];
        *reinterpret_cast<uint4*>(&As[row][c16 * 8]) = a;
        uint4 b = reinterpret_cast<const uint4*>(g_h2 + (size_t)(j0 + row) * KK)[c16];
        *reinterpret_cast<uint4*>(&Bs[bperm_row(row)][c16 * 8]) = b;
    }
    if (t < 128) sc1[t] = g_c1[i0 + t];
    else         sc2[t - 128] = g_c2[j0 + (t - 128)];
    __syncthreads();

    int warp_m = wid >> 2;     // 0..1
    int warp_n = wid & 3;      // 0..3
    int r4 = lane >> 2;        // 0..7
    int q  = lane & 3;         // 0..3
    int c2 = q * 2;

    float acc[4][4][4];
    #pragma unroll
    for (int mt = 0; mt < 4; mt++)
        #pragma unroll
        for (int nt = 0; nt < 4; nt++)
            #pragma unroll
            for (int v = 0; v < 4; v++) acc[mt][nt][v] = 0.0f;

    #pragma unroll
    for (int k = 0; k < 2; k++) {
        int kc = c2 + k * 16;

        uint32_t af[4][4];
        #pragma unroll
        for (int mt = 0; mt < 4; mt++) {
            int row = warp_m * 64 + mt * 16 + r4;
            af[mt][0] = *reinterpret_cast<const uint32_t*>(&As[row    ][kc    ]);
            af[mt][1] = *reinterpret_cast<const uint32_t*>(&As[row + 8][kc    ]);
            af[mt][2] = *reinterpret_cast<const uint32_t*>(&As[row    ][kc + 8]);
            af[mt][3] = *reinterpret_cast<const uint32_t*>(&As[row + 8][kc + 8]);
        }
        uint32_t bf[4][2];
        #pragma unroll
        for (int nt = 0; nt < 4; nt++) {
            int col = warp_n * 32 + nt * 8 + r4;     // natural rows: conflict-free
            bf[nt][0] = *reinterpret_cast<const uint32_t*>(&Bs[col][kc    ]);
            bf[nt][1] = *reinterpret_cast<const uint32_t*>(&Bs[col][kc + 8]);
        }

        #pragma unroll
        for (int mt = 0; mt < 4; mt++)
            #pragma unroll
            for (int nt = 0; nt < 4; nt++)
                hmma16816(acc[mt][nt], af[mt], bf[nt]);
    }

    // --- Epilogue: shuffle-free float4 stores on contiguous global columns ---
    // Thread q owns global cols [cb0, cb0+3] via nt 0,1 and [cb1, cb1+3] via nt 2,3.
    int cb0 = warp_n * 32 + 4 * q;        // tile-relative
    int cb1 = cb0 + 16;
    int cn0[4], cn1[4];
    #pragma unroll
    for (int v = 0; v < 4; v++) { cn0[v] = sc2[cb0 + v]; cn1[v] = sc2[cb1 + v]; }

    #pragma unroll
    for (int mt = 0; mt < 4; mt++) {
        int rA  = warp_m * 64 + mt * 16 + r4;
        int cmA = sc1[rA];
        int cmB = sc1[rA + 8];
        float* rowA = out + (size_t)(i0 + rA)     * (size_t)N2 + (size_t)j0;
        float* rowB = out + (size_t)(i0 + rA + 8) * (size_t)N2 + (size_t)j0;

        float4 o;
        // row rA, cols cb0..cb0+3  (nt0: c0,c1 ; nt1: c0,c1)
        o.x = (cmA == cn0[0]) ? acc[mt][0][0] : 0.0f;
        o.y = (cmA == cn0[1]) ? acc[mt][0][1] : 0.0f;
        o.z = (cmA == cn0[2]) ? acc[mt][1][0] : 0.0f;
        o.w = (cmA == cn0[3]) ? acc[mt][1][1] : 0.0f;
        *reinterpret_cast<float4*>(rowA + cb0) = o;
        // row rA, cols cb1..cb1+3  (nt2,nt3)
        o.x = (cmA == cn1[0]) ? acc[mt][2][0] : 0.0f;
        o.y = (cmA == cn1[1]) ? acc[mt][2][1] : 0.0f;
        o.z = (cmA == cn1[2]) ? acc[mt][3][0] : 0.0f;
        o.w = (cmA == cn1[3]) ? acc[mt][3][1] : 0.0f;
        *reinterpret_cast<float4*>(rowA + cb1) = o;
        // row rA+8, cols cb0..cb0+3  (c2,c3)
        o.x = (cmB == cn0[0]) ? acc[mt][0][2] : 0.0f;
        o.y = (cmB == cn0[1]) ? acc[mt][0][3] : 0.0f;
        o.z = (cmB == cn0[2]) ? acc[mt][1][2] : 0.0f;
        o.w = (cmB == cn0[3]) ? acc[mt][1][3] : 0.0f;
        *reinterpret_cast<float4*>(rowB + cb0) = o;
        // row rA+8, cols cb1..cb1+3
        o.x = (cmB == cn1[0]) ? acc[mt][2][2] : 0.0f;
        o.y = (cmB == cn1[1]) ? acc[mt][2][3] : 0.0f;
        o.z = (cmB == cn1[2]) ? acc[mt][3][2] : 0.0f;
        o.w = (cmB == cn1[3]) ? acc[mt][3][3] : 0.0f;
        *reinterpret_cast<float4*>(rowB + cb1) = o;
    }
}

// ----------------------------------------------------------------------------
extern "C" void kernel_launch(void* const* d_in, const int* in_sizes, int n_in,
                              void* d_out, int out_size)
{
    const float* edges1 = (const float*)d_in[0];
    const float* edges2 = (const float*)d_in[1];
    const float* W1     = (const float*)d_in[2];
    const float* b1     = (const float*)d_in[3];
    const float* W2     = (const float*)d_in[4];
    const float* b2     = (const float*)d_in[5];
    float* out = (float*)d_out;

    int N1 = in_sizes[0] / 4;
    int N2 = in_sizes[1] / 4;

    int totalThreads = (N1 + N2) * 4;
    feat_kernel<<<(totalThreads + 255) / 256, 256>>>(edges1, edges2, N1, N2, W1, b1, W2, b2);

    dim3 grid(N2 / 128, N1 / 128);
    pair_kernel<<<grid, 256>>>(out, N2);
}

// round 6
// speedup vs baseline: 1.2386x; 1.0057x over previous
#include <cuda_runtime.h>
#include <cuda_fp16.h>
#include <cstdint>

// ============================================================================
// EdgeMLP: f = MLP(edges[:, :3]); out[i][j] = (cls1[i]==cls2[j]) * cos(f1[i],f2[j])
// Round 6: HMMA m16n8k16. 64x128 CTA tile, 32x32 warp tile (acc=32 regs ->
// ~64-reg kernel, 4 CTAs/SM) + round-5's permuted-B shuffle-free epilogue.
// ============================================================================

#define N_MAX 8192
#define KK 32

__device__ __half g_h1[N_MAX * KK];
__device__ __half g_h2[N_MAX * KK];
__device__ int    g_c1[N_MAX];
__device__ int    g_c2[N_MAX];

// ----------------------------------------------------------------------------
// Kernel 1: MLP + normalize, 4 threads per row (each 8 of 32 outputs).
// ----------------------------------------------------------------------------
__global__ void __launch_bounds__(256) feat_kernel(
    const float* __restrict__ e1, const float* __restrict__ e2, int N1, int N2,
    const float* __restrict__ W1, const float* __restrict__ b1,
    const float* __restrict__ W2, const float* __restrict__ b2)
{
    __shared__ float sW1[192], sb1[64], sW2[2048], sb2[32];
    int t = threadIdx.x;
    for (int i = t; i < 192;  i += 256) sW1[i] = W1[i];
    if (t < 64) sb1[t] = b1[t];
    for (int i = t; i < 2048; i += 256) sW2[i] = W2[i];
    if (t < 32) sb2[t] = b2[t];
    __syncthreads();

    int gid  = blockIdx.x * 256 + t;
    int row2 = gid >> 2;
    int s    = gid & 3;
    if (row2 >= N1 + N2) return;

    const float* ed; __half* fo; int* co; int row;
    if (row2 < N1) { ed = e1; fo = g_h1; co = g_c1; row = row2; }
    else           { ed = e2; fo = g_h2; co = g_c2; row = row2 - N1; }

    float4 e = reinterpret_cast<const float4*>(ed)[row];

    float f[8];
    #pragma unroll
    for (int q = 0; q < 8; q++) f[q] = sb2[s * 8 + q];

    #pragma unroll 8
    for (int k = 0; k < 64; k++) {
        float h = fmaf(e.x, sW1[k], fmaf(e.y, sW1[64 + k], fmaf(e.z, sW1[128 + k], sb1[k])));
        h = fmaxf(h, 0.0f);
        const float4* w = reinterpret_cast<const float4*>(&sW2[k * 32 + s * 8]);
        float4 w0 = w[0], w1 = w[1];
        f[0] = fmaf(h, w0.x, f[0]); f[1] = fmaf(h, w0.y, f[1]);
        f[2] = fmaf(h, w0.z, f[2]); f[3] = fmaf(h, w0.w, f[3]);
        f[4] = fmaf(h, w1.x, f[4]); f[5] = fmaf(h, w1.y, f[5]);
        f[6] = fmaf(h, w1.z, f[6]); f[7] = fmaf(h, w1.w, f[7]);
    }

    float p = 0.0f;
    #pragma unroll
    for (int q = 0; q < 8; q++) p = fmaf(f[q], f[q], p);
    p += __shfl_xor_sync(0xFFFFFFFFu, p, 1);
    p += __shfl_xor_sync(0xFFFFFFFFu, p, 2);
    float inv = rsqrtf(fmaxf(p, 1e-24f));

    __half2 o[4];
    #pragma unroll
    for (int q = 0; q < 4; q++)
        o[q] = __floats2half2_rn(f[2 * q] * inv, f[2 * q + 1] * inv);
    *reinterpret_cast<uint4*>(fo + (size_t)row * KK + s * 8) = *reinterpret_cast<uint4*>(o);
    if (s == 0) co[row] = (int)e.w;
}

// ----------------------------------------------------------------------------
__device__ __forceinline__ void hmma16816(float c[4], const uint32_t a[4], const uint32_t b[2]) {
    asm volatile(
        "mma.sync.aligned.m16n8k16.row.col.f32.f16.f16.f32 "
        "{%0,%1,%2,%3}, {%4,%5,%6,%7}, {%8,%9}, {%0,%1,%2,%3};"
        : "+f"(c[0]), "+f"(c[1]), "+f"(c[2]), "+f"(c[3])
        : "r"(a[0]), "r"(a[1]), "r"(a[2]), "r"(a[3]), "r"(b[0]), "r"(b[1]));
}

// Column permutation within each 32-col slab:
//   global col bits (s, q1, q0, n1, e) -> smem row bits (s, n1, q1, q0, e)
// => mma tile nt = 2s+n1, fragment col 2q+e holds global col 16s + 4q + 2n1 + e,
//    so thread q owns 4 contiguous global cols per nt-pair.
__device__ __forceinline__ int bperm_row(int j) {
    int jl = j & 31;
    int r  = ((jl >> 4) & 1) * 16 + ((jl >> 1) & 1) * 8 + ((jl >> 2) & 3) * 2 + (jl & 1);
    return (j & ~31) + r;
}

// ----------------------------------------------------------------------------
// Kernel 2: 64x128 tile, 256 threads = 8 warps (2 M x 4 N), warp = 32x32.
// ----------------------------------------------------------------------------
#define RS 40   // smem row stride in halves (80B, conflict-free fragment loads)

__global__ void __launch_bounds__(256, 4) pair_kernel(float* __restrict__ out, int N2)
{
    __shared__ __half As[64][RS];
    __shared__ __half Bs[128][RS];
    __shared__ int sc1[64], sc2[128];

    int t    = threadIdx.x;
    int wid  = t >> 5;
    int lane = t & 31;
    int i0   = blockIdx.y * 64;
    int j0   = blockIdx.x * 128;

    // --- Load tiles: A 64 rows (natural), B 128 rows (column-permuted) ---
    {
        int rowA = t >> 2, c16A = t & 3;        // 256 threads -> 64 rows x 4 chunks
        uint4 a = reinterpret_cast<const uint4*>(g_h1 + (size_t)(i0 + rowA) * KK)[c16A];
        *reinterpret_cast<uint4*>(&As[rowA][c16A * 8]) = a;
        #pragma unroll
        for (int p = 0; p < 2; p++) {
            int v = t + p * 256;                // 0..511 -> 128 rows x 4 chunks
            int row = v >> 2, c16 = v & 3;
            uint4 b = reinterpret_cast<const uint4*>(g_h2 + (size_t)(j0 + row) * KK)[c16];
            *reinterpret_cast<uint4*>(&Bs[bperm_row(row)][c16 * 8]) = b;
        }
    }
    if (t < 64) sc1[t] = g_c1[i0 + t];
    else if (t < 192) sc2[t - 64] = g_c2[j0 + (t - 64)];
    __syncthreads();

    int warp_m = wid >> 2;     // 0..1
    int warp_n = wid & 3;      // 0..3
    int r4 = lane >> 2;        // 0..7
    int q  = lane & 3;         // 0..3
    int c2 = q * 2;

    float acc[2][4][4];
    #pragma unroll
    for (int mt = 0; mt < 2; mt++)
        #pragma unroll
        for (int nt = 0; nt < 4; nt++)
            #pragma unroll
            for (int v = 0; v < 4; v++) acc[mt][nt][v] = 0.0f;

    #pragma unroll
    for (int k = 0; k < 2; k++) {
        int kc = c2 + k * 16;

        uint32_t af[2][4];
        #pragma unroll
        for (int mt = 0; mt < 2; mt++) {
            int row = warp_m * 32 + mt * 16 + r4;
            af[mt][0] = *reinterpret_cast<const uint32_t*>(&As[row    ][kc    ]);
            af[mt][1] = *reinterpret_cast<const uint32_t*>(&As[row + 8][kc    ]);
            af[mt][2] = *reinterpret_cast<const uint32_t*>(&As[row    ][kc + 8]);
            af[mt][3] = *reinterpret_cast<const uint32_t*>(&As[row + 8][kc + 8]);
        }
        uint32_t bf[4][2];
        #pragma unroll
        for (int nt = 0; nt < 4; nt++) {
            int col = warp_n * 32 + nt * 8 + r4;     // natural rows: conflict-free
            bf[nt][0] = *reinterpret_cast<const uint32_t*>(&Bs[col][kc    ]);
            bf[nt][1] = *reinterpret_cast<const uint32_t*>(&Bs[col][kc + 8]);
        }

        #pragma unroll
        for (int mt = 0; mt < 2; mt++)
            #pragma unroll
            for (int nt = 0; nt < 4; nt++)
                hmma16816(acc[mt][nt], af[mt], bf[nt]);
    }

    // --- Epilogue: shuffle-free float4 stores on contiguous global columns ---
    int cb0 = warp_n * 32 + 4 * q;        // tile-relative col base (nt0,nt1)
    int cb1 = cb0 + 16;                   // (nt2,nt3)
    int cn0[4], cn1[4];
    #pragma unroll
    for (int v = 0; v < 4; v++) { cn0[v] = sc2[cb0 + v]; cn1[v] = sc2[cb1 + v]; }

    #pragma unroll
    for (int mt = 0; mt < 2; mt++) {
        int rA  = warp_m * 32 + mt * 16 + r4;
        int cmA = sc1[rA];
        int cmB = sc1[rA + 8];
        float* rowA = out + (size_t)(i0 + rA)     * (size_t)N2 + (size_t)j0;
        float* rowB = out + (size_t)(i0 + rA + 8) * (size_t)N2 + (size_t)j0;

        float4 o;
        o.x = (cmA == cn0[0]) ? acc[mt][0][0] : 0.0f;
        o.y = (cmA == cn0[1]) ? acc[mt][0][1] : 0.0f;
        o.z = (cmA == cn0[2]) ? acc[mt][1][0] : 0.0f;
        o.w = (cmA == cn0[3]) ? acc[mt][1][1] : 0.0f;
        *reinterpret_cast<float4*>(rowA + cb0) = o;

        o.x = (cmA == cn1[0]) ? acc[mt][2][0] : 0.0f;
        o.y = (cmA == cn1[1]) ? acc[mt][2][1] : 0.0f;
        o.z = (cmA == cn1[2]) ? acc[mt][3][0] : 0.0f;
        o.w = (cmA == cn1[3]) ? acc[mt][3][1] : 0.0f;
        *reinterpret_cast<float4*>(rowA + cb1) = o;

        o.x = (cmB == cn0[0]) ? acc[mt][0][2] : 0.0f;
        o.y = (cmB == cn0[1]) ? acc[mt][0][3] : 0.0f;
        o.z = (cmB == cn0[2]) ? acc[mt][1][2] : 0.0f;
        o.w = (cmB == cn0[3]) ? acc[mt][1][3] : 0.0f;
        *reinterpret_cast<float4*>(rowB + cb0) = o;

        o.x = (cmB == cn1[0]) ? acc[mt][2][2] : 0.0f;
        o.y = (cmB == cn1[1]) ? acc[mt][2][3] : 0.0f;
        o.z = (cmB == cn1[2]) ? acc[mt][3][2] : 0.0f;
        o.w = (cmB == cn1[3]) ? acc[mt][3][3] : 0.0f;
        *reinterpret_cast<float4*>(rowB + cb1) = o;
    }
}

// ----------------------------------------------------------------------------
extern "C" void kernel_launch(void* const* d_in, const int* in_sizes, int n_in,
                              void* d_out, int out_size)
{
    const float* edges1 = (const float*)d_in[0];
    const float* edges2 = (const float*)d_in[1];
    const float* W1     = (const float*)d_in[2];
    const float* b1     = (const float*)d_in[3];
    const float* W2     = (const float*)d_in[4];
    const float* b2     = (const float*)d_in[5];
    float* out = (float*)d_out;

    int N1 = in_sizes[0] / 4;
    int N2 = in_sizes[1] / 4;

    int totalThreads = (N1 + N2) * 4;
    feat_kernel<<<(totalThreads + 255) / 256, 256>>>(edges1, edges2, N1, N2, W1, b1, W2, b2);

    dim3 grid(N2 / 128, N1 / 64);
    pair_kernel<<<grid, 256>>>(out, N2);
}

// round 7
// speedup vs baseline: 1.3283x; 1.0725x over previous
#include <cuda_runtime.h>
#include <cuda_fp16.h>
#include <cstdint>

// ============================================================================
// EdgeMLP: f = MLP(edges[:, :3]); out[i][j] = (cls1[i]==cls2[j]) * cos(f1[i],f2[j])
// Round 7: HMMA m16n8k16, 64x128 CTA tile, 32x32 warp tile. NEW: 256-bit
// stores (st.global.v8.b32, Blackwell) + permutation giving each thread 8
// contiguous output columns -> full 128B store wavefronts (halves L1 slots).
// ============================================================================

#define N_MAX 8192
#define KK 32

__device__ __half g_h1[N_MAX * KK];
__device__ __half g_h2[N_MAX * KK];
__device__ int    g_c1[N_MAX];
__device__ int    g_c2[N_MAX];

// ----------------------------------------------------------------------------
// Kernel 1: MLP + normalize, 4 threads per row (each 8 of 32 outputs).
// ----------------------------------------------------------------------------
__global__ void __launch_bounds__(256) feat_kernel(
    const float* __restrict__ e1, const float* __restrict__ e2, int N1, int N2,
    const float* __restrict__ W1, const float* __restrict__ b1,
    const float* __restrict__ W2, const float* __restrict__ b2)
{
    __shared__ float sW1[192], sb1[64], sW2[2048], sb2[32];
    int t = threadIdx.x;
    for (int i = t; i < 192;  i += 256) sW1[i] = W1[i];
    if (t < 64) sb1[t] = b1[t];
    for (int i = t; i < 2048; i += 256) sW2[i] = W2[i];
    if (t < 32) sb2[t] = b2[t];
    __syncthreads();

    int gid  = blockIdx.x * 256 + t;
    int row2 = gid >> 2;
    int s    = gid & 3;
    if (row2 >= N1 + N2) return;

    const float* ed; __half* fo; int* co; int row;
    if (row2 < N1) { ed = e1; fo = g_h1; co = g_c1; row = row2; }
    else           { ed = e2; fo = g_h2; co = g_c2; row = row2 - N1; }

    float4 e = reinterpret_cast<const float4*>(ed)[row];

    float f[8];
    #pragma unroll
    for (int q = 0; q < 8; q++) f[q] = sb2[s * 8 + q];

    #pragma unroll 8
    for (int k = 0; k < 64; k++) {
        float h = fmaf(e.x, sW1[k], fmaf(e.y, sW1[64 + k], fmaf(e.z, sW1[128 + k], sb1[k])));
        h = fmaxf(h, 0.0f);
        const float4* w = reinterpret_cast<const float4*>(&sW2[k * 32 + s * 8]);
        float4 w0 = w[0], w1 = w[1];
        f[0] = fmaf(h, w0.x, f[0]); f[1] = fmaf(h, w0.y, f[1]);
        f[2] = fmaf(h, w0.z, f[2]); f[3] = fmaf(h, w0.w, f[3]);
        f[4] = fmaf(h, w1.x, f[4]); f[5] = fmaf(h, w1.y, f[5]);
        f[6] = fmaf(h, w1.z, f[6]); f[7] = fmaf(h, w1.w, f[7]);
    }

    float p = 0.0f;
    #pragma unroll
    for (int q = 0; q < 8; q++) p = fmaf(f[q], f[q], p);
    p += __shfl_xor_sync(0xFFFFFFFFu, p, 1);
    p += __shfl_xor_sync(0xFFFFFFFFu, p, 2);
    float inv = rsqrtf(fmaxf(p, 1e-24f));

    __half2 o[4];
    #pragma unroll
    for (int q = 0; q < 4; q++)
        o[q] = __floats2half2_rn(f[2 * q] * inv, f[2 * q + 1] * inv);
    *reinterpret_cast<uint4*>(fo + (size_t)row * KK + s * 8) = *reinterpret_cast<uint4*>(o);
    if (s == 0) co[row] = (int)e.w;
}

// ----------------------------------------------------------------------------
__device__ __forceinline__ void hmma16816(float c[4], const uint32_t a[4], const uint32_t b[2]) {
    asm volatile(
        "mma.sync.aligned.m16n8k16.row.col.f32.f16.f16.f32 "
        "{%0,%1,%2,%3}, {%4,%5,%6,%7}, {%8,%9}, {%0,%1,%2,%3};"
        : "+f"(c[0]), "+f"(c[1]), "+f"(c[2]), "+f"(c[3])
        : "r"(a[0]), "r"(a[1]), "r"(a[2]), "r"(a[3]), "r"(b[0]), "r"(b[1]));
}

// 256-bit store (Blackwell sm_100+): one lane writes 32B; 4 lanes with the
// same row cover a full 128B line in one wavefront.
__device__ __forceinline__ void stg256(float* p, const float v[8]) {
    asm volatile(
        "st.global.v8.b32 [%0], {%1,%2,%3,%4,%5,%6,%7,%8};"
        :: "l"(p),
           "r"(__float_as_uint(v[0])), "r"(__float_as_uint(v[1])),
           "r"(__float_as_uint(v[2])), "r"(__float_as_uint(v[3])),
           "r"(__float_as_uint(v[4])), "r"(__float_as_uint(v[5])),
           "r"(__float_as_uint(v[6])), "r"(__float_as_uint(v[7]))
        : "memory");
}

// Column permutation within each 32-col slab:
//   global col j (bits q1 q0 | n1 n0 | e) -> accumulator position:
//   thread q = j>>3 owns cols 8q..8q+7, with col = 8q + 2*nt + e.
//   Required smem row: r = nt*8 + 2q + e.
__device__ __forceinline__ int bperm_row(int j) {
    int jl = j & 31;
    int r  = ((jl >> 1) & 3) * 8 + ((jl >> 3) & 3) * 2 + (jl & 1);
    return (j & ~31) + r;
}

// ----------------------------------------------------------------------------
// Kernel 2: 64x128 tile, 256 threads = 8 warps (2 M x 4 N), warp = 32x32.
// ----------------------------------------------------------------------------
#define RS 40   // smem row stride in halves (80B, conflict-free fragment loads)

__global__ void __launch_bounds__(256, 4) pair_kernel(float* __restrict__ out, int N2)
{
    __shared__ __half As[64][RS];
    __shared__ __half Bs[128][RS];
    __shared__ int sc1[64], sc2[128];

    int t    = threadIdx.x;
    int wid  = t >> 5;
    int lane = t & 31;
    int i0   = blockIdx.y * 64;
    int j0   = blockIdx.x * 128;

    // --- Load tiles: A 64 rows (natural), B 128 rows (column-permuted) ---
    {
        int rowA = t >> 2, c16A = t & 3;
        uint4 a = reinterpret_cast<const uint4*>(g_h1 + (size_t)(i0 + rowA) * KK)[c16A];
        *reinterpret_cast<uint4*>(&As[rowA][c16A * 8]) = a;
        #pragma unroll
        for (int p = 0; p < 2; p++) {
            int v = t + p * 256;
            int row = v >> 2, c16 = v & 3;
            uint4 b = reinterpret_cast<const uint4*>(g_h2 + (size_t)(j0 + row) * KK)[c16];
            *reinterpret_cast<uint4*>(&Bs[bperm_row(row)][c16 * 8]) = b;
        }
    }
    if (t < 64) sc1[t] = g_c1[i0 + t];
    else if (t < 192) sc2[t - 64] = g_c2[j0 + (t - 64)];
    __syncthreads();

    int warp_m = wid >> 2;     // 0..1
    int warp_n = wid & 3;      // 0..3
    int r4 = lane >> 2;        // 0..7
    int q  = lane & 3;         // 0..3
    int c2 = q * 2;

    float acc[2][4][4];
    #pragma unroll
    for (int mt = 0; mt < 2; mt++)
        #pragma unroll
        for (int nt = 0; nt < 4; nt++)
            #pragma unroll
            for (int v = 0; v < 4; v++) acc[mt][nt][v] = 0.0f;

    #pragma unroll
    for (int k = 0; k < 2; k++) {
        int kc = c2 + k * 16;

        uint32_t af[2][4];
        #pragma unroll
        for (int mt = 0; mt < 2; mt++) {
            int row = warp_m * 32 + mt * 16 + r4;
            af[mt][0] = *reinterpret_cast<const uint32_t*>(&As[row    ][kc    ]);
            af[mt][1] = *reinterpret_cast<const uint32_t*>(&As[row + 8][kc    ]);
            af[mt][2] = *reinterpret_cast<const uint32_t*>(&As[row    ][kc + 8]);
            af[mt][3] = *reinterpret_cast<const uint32_t*>(&As[row + 8][kc + 8]);
        }
        uint32_t bf[4][2];
        #pragma unroll
        for (int nt = 0; nt < 4; nt++) {
            int col = warp_n * 32 + nt * 8 + r4;
            bf[nt][0] = *reinterpret_cast<const uint32_t*>(&Bs[col][kc    ]);
            bf[nt][1] = *reinterpret_cast<const uint32_t*>(&Bs[col][kc + 8]);
        }

        #pragma unroll
        for (int mt = 0; mt < 2; mt++)
            #pragma unroll
            for (int nt = 0; nt < 4; nt++)
                hmma16816(acc[mt][nt], af[mt], bf[nt]);
    }

    // --- Epilogue: per-thread 8 contiguous cols, one STG.256 per row ---
    int cb = warp_n * 32 + 8 * q;         // tile-relative col base
    int cn[8];
    #pragma unroll
    for (int v = 0; v < 8; v++) cn[v] = sc2[cb + v];

    #pragma unroll
    for (int mt = 0; mt < 2; mt++) {
        int rA  = warp_m * 32 + mt * 16 + r4;
        int cmA = sc1[rA];
        int cmB = sc1[rA + 8];
        float* rowA = out + (size_t)(i0 + rA)     * (size_t)N2 + (size_t)(j0 + cb);
        float* rowB = out + (size_t)(i0 + rA + 8) * (size_t)N2 + (size_t)(j0 + cb);

        float va[8], vb[8];
        #pragma unroll
        for (int nt = 0; nt < 4; nt++) {
            va[2 * nt]     = (cmA == cn[2 * nt])     ? acc[mt][nt][0] : 0.0f;
            va[2 * nt + 1] = (cmA == cn[2 * nt + 1]) ? acc[mt][nt][1] : 0.0f;
            vb[2 * nt]     = (cmB == cn[2 * nt])     ? acc[mt][nt][2] : 0.0f;
            vb[2 * nt + 1] = (cmB == cn[2 * nt + 1]) ? acc[mt][nt][3] : 0.0f;
        }
        stg256(rowA, va);
        stg256(rowB, vb);
    }
}

// ----------------------------------------------------------------------------
extern "C" void kernel_launch(void* const* d_in, const int* in_sizes, int n_in,
                              void* d_out, int out_size)
{
    const float* edges1 = (const float*)d_in[0];
    const float* edges2 = (const float*)d_in[1];
    const float* W1     = (const float*)d_in[2];
    const float* b1     = (const float*)d_in[3];
    const float* W2     = (const float*)d_in[4];
    const float* b2     = (const float*)d_in[5];
    float* out = (float*)d_out;

    int N1 = in_sizes[0] / 4;
    int N2 = in_sizes[1] / 4;

    int totalThreads = (N1 + N2) * 4;
    feat_kernel<<<(totalThreads + 255) / 256, 256>>>(edges1, edges2, N1, N2, W1, b1, W2, b2);

    dim3 grid(N2 / 128, N1 / 64);
    pair_kernel<<<grid, 256>>>(out, N2);
}